// round 2
// baseline (speedup 1.0000x reference)
#include <cuda_runtime.h>

#define DIMC 256
#define NPIX 4096
#define BATCH 16
#define HID 512
#define NH 8
#define DH 64

// ---------------- scratch (device globals, no allocation) ----------------
__device__ float g_Gp[4 * BATCH * DIMC * DIMC];  // split-K partials of X X^T
__device__ float g_G [BATCH * DIMC * DIMC];      // G_b = X X^T
__device__ float g_P [BATCH * HID * DIMC];       // P_b = Wk @ G_b
__device__ float g_C [BATCH * NH * DH * DH];     // C_bh = P_bh @ Wv_h^T
__device__ float g_M [BATCH * HID * DIMC];       // M_bh = C^T @ Wq_h / 8
__device__ float g_A [BATCH * DIMC * DIMC];      // A_b = W_out @ M_b

// ---------------- generic 64x64 fp32 tile GEMM -----------------
// Computes a 64x64 tile: acc[m][n] += sum_k A(m,k) * B(k,n)
// A_KC:  A element (r,k) at A[r*lda + k]   (k contiguous -> transpose-store)
// !A_KC: A element (r,k) at A[k*lda + r]   (r contiguous -> direct store)
// Same for B with (k,n).
template<bool A_KC, bool B_KC>
__device__ __forceinline__ void gemm_tile(const float* __restrict__ A, int lda,
                                          const float* __restrict__ B, int ldb,
                                          int K, float acc[4][4], int tid)
{
    __shared__ float As[16][64];
    __shared__ float Bs[16][64];
    const int tx = tid & 15;
    const int ty = tid >> 4;

    for (int kb = 0; kb < K; kb += 16) {
        __syncthreads();
        // ---- load A tile ----
        if (A_KC) {
            int r  = tid & 63;
            int kq = tid >> 6;              // 0..3, each covers 4 k's
            float4 v = *(const float4*)(A + (size_t)r * lda + kb + kq * 4);
            As[kq*4+0][r] = v.x; As[kq*4+1][r] = v.y;
            As[kq*4+2][r] = v.z; As[kq*4+3][r] = v.w;
        } else {
            int c = (tid & 15) * 4;
            int k = tid >> 4;               // 0..15
            *(float4*)&As[k][c] = *(const float4*)(A + (size_t)(kb + k) * lda + c);
        }
        // ---- load B tile ----
        if (B_KC) {
            int r  = tid & 63;
            int kq = tid >> 6;
            float4 v = *(const float4*)(B + (size_t)r * ldb + kb + kq * 4);
            Bs[kq*4+0][r] = v.x; Bs[kq*4+1][r] = v.y;
            Bs[kq*4+2][r] = v.z; Bs[kq*4+3][r] = v.w;
        } else {
            int c = (tid & 15) * 4;
            int k = tid >> 4;
            *(float4*)&Bs[k][c] = *(const float4*)(B + (size_t)(kb + k) * ldb + c);
        }
        __syncthreads();
        // ---- 4x4 micro-kernel ----
        #pragma unroll
        for (int k = 0; k < 16; ++k) {
            float4 av = *(const float4*)&As[k][ty * 4];
            float4 bv = *(const float4*)&Bs[k][tx * 4];
            float a[4] = {av.x, av.y, av.z, av.w};
            float b[4] = {bv.x, bv.y, bv.z, bv.w};
            #pragma unroll
            for (int i = 0; i < 4; ++i)
                #pragma unroll
                for (int j = 0; j < 4; ++j)
                    acc[i][j] += a[i] * b[j];
        }
    }
}

// ---------------- kernel 1: split-K partial SYRK G = X X^T ----------------
// grid: (10 upper-tri tile pairs, 4 k-slices, 16 batches), block 256
__global__ void syrk_kernel(const float* __restrict__ x)
{
    int p  = blockIdx.x;
    int ks = blockIdx.y;
    int b  = blockIdx.z;
    int ti, tj;
    if      (p < 4) { ti = 0; tj = p;     }
    else if (p < 7) { ti = 1; tj = p - 3; }
    else if (p < 9) { ti = 2; tj = p - 5; }
    else            { ti = 3; tj = 3;     }

    const float* Xb = x + (size_t)b * DIMC * NPIX;
    const float* Ab = Xb + (size_t)ti * 64 * NPIX + ks * 1024;
    const float* Bb = Xb + (size_t)tj * 64 * NPIX + ks * 1024;

    float acc[4][4] = {};
    int tid = threadIdx.x;
    gemm_tile<true, true>(Ab, NPIX, Bb, NPIX, 1024, acc, tid);

    float* Gp = g_Gp + ((size_t)ks * BATCH + b) * DIMC * DIMC;
    int tx = tid & 15, ty = tid >> 4;
    #pragma unroll
    for (int i = 0; i < 4; ++i) {
        #pragma unroll
        for (int j = 0; j < 4; ++j) {
            int m = ti * 64 + ty * 4 + i;
            int n = tj * 64 + tx * 4 + j;
            Gp[m * DIMC + n] = acc[i][j];
            if (ti != tj) Gp[n * DIMC + m] = acc[i][j];   // symmetric mirror
        }
    }
}

// ---------------- kernel 2: reduce 4 split-K slices (deterministic) -------
__global__ void reduce_g_kernel()
{
    int idx = blockIdx.x * blockDim.x + threadIdx.x;   // 262144 float4s
    const float4* p0 = (const float4*)g_Gp;
    const size_t S = (size_t)BATCH * DIMC * DIMC / 4;  // float4 count per slice
    float4 a = p0[idx], b = p0[idx + S], c = p0[idx + 2*S], d = p0[idx + 3*S];
    float4 r;
    r.x = a.x + b.x + c.x + d.x;
    r.y = a.y + b.y + c.y + d.y;
    r.z = a.z + b.z + c.z + d.z;
    r.w = a.w + b.w + c.w + d.w;
    ((float4*)g_G)[idx] = r;
}

// ---------------- kernel 3: P_b = Wk @ G_b  [512,256] ----------------
// grid: (ntile=4, mtile=8, batch=16)
__global__ void s1_kernel(const float* __restrict__ w_qkv)
{
    int nt = blockIdx.x, mt = blockIdx.y, b = blockIdx.z;
    const float* A = w_qkv + (size_t)HID * DIMC + (size_t)mt * 64 * DIMC; // Wk rows
    const float* B = g_G + (size_t)b * DIMC * DIMC + nt * 64;
    float acc[4][4] = {};
    int tid = threadIdx.x;
    gemm_tile<true, false>(A, DIMC, B, DIMC, DIMC, acc, tid);
    float* C = g_P + (size_t)b * HID * DIMC;
    int tx = tid & 15, ty = tid >> 4;
    #pragma unroll
    for (int i = 0; i < 4; ++i)
        #pragma unroll
        for (int j = 0; j < 4; ++j)
            C[(mt*64 + ty*4 + i) * DIMC + nt*64 + tx*4 + j] = acc[i][j];
}

// ---------------- kernel 4: C_bh = P_bh @ Wv_h^T  [64,64] ----------------
// grid: (1,1,128)
__global__ void s2_kernel(const float* __restrict__ w_qkv)
{
    int bh = blockIdx.z;
    int b = bh >> 3, h = bh & 7;
    const float* A = g_P + (size_t)b * HID * DIMC + (size_t)h * 64 * DIMC;
    const float* B = w_qkv + (size_t)2 * HID * DIMC + (size_t)h * 64 * DIMC; // Wv rows (n,k)
    float acc[4][4] = {};
    int tid = threadIdx.x;
    gemm_tile<true, true>(A, DIMC, B, DIMC, DIMC, acc, tid);
    float* C = g_C + (size_t)bh * DH * DH;
    int tx = tid & 15, ty = tid >> 4;
    #pragma unroll
    for (int i = 0; i < 4; ++i)
        #pragma unroll
        for (int j = 0; j < 4; ++j)
            C[(ty*4 + i) * DH + tx*4 + j] = acc[i][j];
}

// ---------------- kernel 5: M_bh = C_bh^T @ Wq_h / 8  [64,256] ----------------
// grid: (ntile=4, 1, 128)
__global__ void s3_kernel(const float* __restrict__ w_qkv)
{
    int nt = blockIdx.x, bh = blockIdx.z;
    int b = bh >> 3, h = bh & 7;
    const float* A = g_C + (size_t)bh * DH * DH;                 // (e,d) = C[d*64+e] -> NC, lda=64
    const float* B = w_qkv + (size_t)h * 64 * DIMC + nt * 64;    // Wq_h (d,c) -> NC, ldb=256
    float acc[4][4] = {};
    int tid = threadIdx.x;
    gemm_tile<false, false>(A, DH, B, DIMC, DH, acc, tid);
    float* C = g_M + (size_t)b * HID * DIMC + (size_t)h * 64 * DIMC;
    int tx = tid & 15, ty = tid >> 4;
    #pragma unroll
    for (int i = 0; i < 4; ++i)
        #pragma unroll
        for (int j = 0; j < 4; ++j)
            C[(ty*4 + i) * DIMC + nt*64 + tx*4 + j] = acc[i][j] * 0.125f;  // 1/sqrt(64)
}

// ---------------- kernel 6: A_b = W_out @ M_b  [256,256] ----------------
// grid: (ntile=4, mtile=4, 16)
__global__ void s4_kernel(const float* __restrict__ w_out)
{
    int nt = blockIdx.x, mt = blockIdx.y, b = blockIdx.z;
    const float* A = w_out + (size_t)mt * 64 * HID;              // KC, lda=512, K=512
    const float* B = g_M + (size_t)b * HID * DIMC + nt * 64;     // NC, ldb=256
    float acc[4][4] = {};
    int tid = threadIdx.x;
    gemm_tile<true, false>(A, HID, B, DIMC, HID, acc, tid);
    float* C = g_A + (size_t)b * DIMC * DIMC;
    int tx = tid & 15, ty = tid >> 4;
    #pragma unroll
    for (int i = 0; i < 4; ++i)
        #pragma unroll
        for (int j = 0; j < 4; ++j)
            C[(mt*64 + ty*4 + i) * DIMC + nt*64 + tx*4 + j] = acc[i][j];
}

// ---------------- kernel 7: out_b = A_b @ X_b + b_out  [256,4096] ----------------
// grid: (ntile=64, mtile=4, 16)
__global__ void final_kernel(const float* __restrict__ x,
                             const float* __restrict__ b_out,
                             float* __restrict__ out)
{
    int nt = blockIdx.x, mt = blockIdx.y, b = blockIdx.z;
    const float* A = g_A + (size_t)b * DIMC * DIMC + (size_t)mt * 64 * DIMC;  // KC, lda=256
    const float* B = x + (size_t)b * DIMC * NPIX + nt * 64;                   // NC, ldb=4096
    float acc[4][4] = {};
    int tid = threadIdx.x;
    gemm_tile<true, false>(A, DIMC, B, NPIX, DIMC, acc, tid);
    float* C = out + (size_t)b * DIMC * NPIX;
    int tx = tid & 15, ty = tid >> 4;
    #pragma unroll
    for (int i = 0; i < 4; ++i) {
        int m = mt*64 + ty*4 + i;
        float bias = b_out[m];
        #pragma unroll
        for (int j = 0; j < 4; ++j)
            C[(size_t)m * NPIX + nt*64 + tx*4 + j] = acc[i][j] + bias;
    }
}

// ---------------- launch ----------------
extern "C" void kernel_launch(void* const* d_in, const int* in_sizes, int n_in,
                              void* d_out, int out_size)
{
    const float* x      = (const float*)d_in[0];
    const float* w_qkv  = (const float*)d_in[1];
    const float* w_out  = (const float*)d_in[2];
    const float* b_out  = (const float*)d_in[3];
    float* out = (float*)d_out;

    syrk_kernel  <<<dim3(10, 4, 16), 256>>>(x);
    reduce_g_kernel<<<1024, 256>>>();
    s1_kernel    <<<dim3(4, 8, 16), 256>>>(w_qkv);
    s2_kernel    <<<dim3(1, 1, 128), 256>>>(w_qkv);
    s3_kernel    <<<dim3(4, 1, 128), 256>>>(w_qkv);
    s4_kernel    <<<dim3(4, 4, 16), 256>>>(w_out);
    final_kernel <<<dim3(64, 4, 16), 256>>>(x, b_out, out);
}

// round 4
// speedup vs baseline: 1.4240x; 1.4240x over previous
#include <cuda_runtime.h>
#include <cuda_bf16.h>
#include <cstdint>

#define DIMC 256
#define NPIX 4096
#define BATCH 16
#define HID 512
#define NH 8
#define DH 64

#define BK 32
#define PAD 4
#define LROW (BK + PAD)    // bf16 elems per smem row

// ---------------- scratch (device globals, no allocation) ----------------
__device__ float g_Gp[4 * BATCH * DIMC * DIMC];  // split-K partials of G
__device__ float g_G [BATCH * DIMC * DIMC];      // G_b = X X^T
__device__ float g_P [BATCH * HID * DIMC];       // P_b = Wk @ G_b
__device__ float g_C [BATCH * NH * DH * DH];     // C_bh = P_bh @ Wv_h^T
__device__ float g_M [BATCH * HID * DIMC];       // M[h*64+e][c] = (C^T Wq /8)
__device__ float g_A [BATCH * DIMC * DIMC];      // A_b = W_out @ M_b

// ---------------- helpers ----------------
__device__ __forceinline__ void split2(float v, __nv_bfloat16& h, __nv_bfloat16& l) {
    h = __float2bfloat16(v);
    l = __float2bfloat16(v - __bfloat162float(h));
}

__device__ __forceinline__ void mma16816(float c[4],
                                         uint32_t a0, uint32_t a1, uint32_t a2, uint32_t a3,
                                         uint32_t b0, uint32_t b1) {
    asm volatile(
        "mma.sync.aligned.m16n8k16.row.col.f32.bf16.bf16.f32 "
        "{%0,%1,%2,%3},{%4,%5,%6,%7},{%8,%9},{%0,%1,%2,%3};"
        : "+f"(c[0]), "+f"(c[1]), "+f"(c[2]), "+f"(c[3])
        : "r"(a0), "r"(a1), "r"(a2), "r"(a3), "r"(b0), "r"(b1));
}

// K-contiguous loader: tile(r,k) = src[r*ld + k0 + k], 128 rows x 32 k, fp32 -> hi/lo bf16
__device__ __forceinline__ void load_kc(const float* __restrict__ src, int ld, int rows,
                                        int k0, __nv_bfloat16* hi, __nv_bfloat16* lo, int tid) {
    #pragma unroll
    for (int i = 0; i < 4; ++i) {
        int idx = tid + i * 256;          // 0..1023
        int r = idx >> 3, q = idx & 7;
        int rs = r < rows ? r : 0;
        float4 v = *(const float4*)(src + (size_t)rs * ld + k0 + q * 4);
        int o = r * LROW + q * 4;
        split2(v.x, hi[o+0], lo[o+0]);
        split2(v.y, hi[o+1], lo[o+1]);
        split2(v.z, hi[o+2], lo[o+2]);
        split2(v.w, hi[o+3], lo[o+3]);
    }
}

// MN-contiguous loader: tile(r,k) = src[(k0+k)*ld + r]
__device__ __forceinline__ void load_mn(const float* __restrict__ src, int ld, int rows,
                                        int k0, __nv_bfloat16* hi, __nv_bfloat16* lo, int tid) {
    #pragma unroll
    for (int i = 0; i < 16; ++i) {
        int idx = tid + i * 256;          // 0..4095
        int r = idx & 127, k = idx >> 7;
        int rs = r < rows ? r : 0;
        float v = src[(size_t)(k0 + k) * ld + rs];
        int o = r * LROW + k;
        split2(v, hi[o], lo[o]);
    }
}

// ---------------- modes ----------------
#define MODE_SYRK  0
#define MODE_S1    1
#define MODE_S2    2
#define MODE_S3    3
#define MODE_S4    4
#define MODE_FINAL 5

__global__ void __launch_bounds__(256)
mma_kernel(int mode, const float* __restrict__ x, const float* __restrict__ w_qkv,
           const float* __restrict__ w_out, const float* __restrict__ b_out,
           float* __restrict__ out)
{
    __shared__ __nv_bfloat16 As_hi[128 * LROW];
    __shared__ __nv_bfloat16 As_lo[128 * LROW];
    __shared__ __nv_bfloat16 Bs_hi[128 * LROW];
    __shared__ __nv_bfloat16 Bs_lo[128 * LROW];

    const int tid = threadIdx.x;
    const int lane = tid & 31, wid = tid >> 5;
    const int wm = wid >> 2, wn = wid & 3;   // 2 x 4 warp grid
    const int m0 = wm * 64, n0 = wn * 32;
    const int bx = blockIdx.x;

    // ---- decode job ----
    const float *A, *B;
    int lda, ldb, K, Ar, Br;
    bool a_mn = false, b_mn = false;
    int orows = 128, ocols = 128, ldo;
    float esc = 1.0f;
    const float* bias = nullptr;
    float* eo;
    float* em = nullptr;   // mirror (SYRK off-diag)

    if (mode == MODE_SYRK) {
        int p = bx % 3, ks = (bx / 3) & 3, b = bx / 12;
        int ti = (p == 2) ? 1 : 0;
        int tj = (p == 0) ? 0 : 1;
        A = x + ((size_t)b * DIMC + ti * 128) * NPIX + ks * 1024;
        B = x + ((size_t)b * DIMC + tj * 128) * NPIX + ks * 1024;
        lda = NPIX; ldb = NPIX; K = 1024; Ar = 128; Br = 128;
        ldo = DIMC;
        float* Gp = g_Gp + ((size_t)ks * BATCH + b) * DIMC * DIMC;
        eo = Gp + (size_t)ti * 128 * DIMC + tj * 128;
        if (ti != tj) em = Gp + (size_t)tj * 128 * DIMC + ti * 128;
    } else if (mode == MODE_S1) {
        int nt = bx & 1, mt = (bx >> 1) & 3, b = bx >> 3;
        A = w_qkv + (size_t)(HID + mt * 128) * DIMC;
        B = g_G + (size_t)b * DIMC * DIMC + (size_t)nt * 128 * DIMC;  // G symmetric
        lda = DIMC; ldb = DIMC; K = DIMC; Ar = 128; Br = 128; ldo = DIMC;
        eo = g_P + (size_t)b * HID * DIMC + (size_t)mt * 128 * DIMC + nt * 128;
    } else if (mode == MODE_S2) {
        int h = bx & 7, b = bx >> 3;
        A = g_P + (size_t)b * HID * DIMC + (size_t)h * 64 * DIMC;
        B = w_qkv + (size_t)(2 * HID + h * 64) * DIMC;
        lda = DIMC; ldb = DIMC; K = DIMC; Ar = 64; Br = 64;
        orows = 64; ocols = 64; ldo = 64;
        eo = g_C + (size_t)bx * DH * DH;
    } else if (mode == MODE_S3) {
        int nt = bx & 1, bh = bx >> 1, h = bh & 7, b = bh >> 3;
        A = g_C + (size_t)bh * DH * DH;                 // A(e,d)=C[d*64+e]
        B = w_qkv + (size_t)h * 64 * DIMC + nt * 128;   // B(c,d)=wq[(h64+d)*256+c]
        a_mn = true; b_mn = true;
        lda = 64; ldb = DIMC; K = DH; Ar = 64; Br = 128;
        orows = 64; ocols = 128; ldo = DIMC; esc = 0.125f;
        eo = g_M + (size_t)b * HID * DIMC + (size_t)h * 64 * DIMC + nt * 128;
    } else if (mode == MODE_S4) {
        int nt = bx & 1, mt = (bx >> 1) & 1, b = bx >> 2;
        A = w_out + (size_t)mt * 128 * HID;
        B = g_M + (size_t)b * HID * DIMC + nt * 128;    // B(c,j)=M[j][c]
        b_mn = true;
        lda = HID; ldb = DIMC; K = HID; Ar = 128; Br = 128; ldo = DIMC;
        eo = g_A + (size_t)b * DIMC * DIMC + (size_t)mt * 128 * DIMC + nt * 128;
    } else {  // MODE_FINAL
        int nt = bx & 31, mt = (bx >> 5) & 1, b = bx >> 6;
        A = g_A + (size_t)b * DIMC * DIMC + (size_t)mt * 128 * DIMC;
        B = x + (size_t)b * DIMC * NPIX + nt * 128;     // B(pix,c)=x[c][pix]
        b_mn = true;
        lda = DIMC; ldb = NPIX; K = DIMC; Ar = 128; Br = 128; ldo = NPIX;
        bias = b_out + mt * 128;
        eo = out + (size_t)b * DIMC * NPIX + (size_t)mt * 128 * NPIX + nt * 128;
    }

    float acc[4][4][4];
    #pragma unroll
    for (int a = 0; a < 4; ++a)
        #pragma unroll
        for (int b2 = 0; b2 < 4; ++b2)
            #pragma unroll
            for (int c = 0; c < 4; ++c) acc[a][b2][c] = 0.0f;

    // ---- main loop ----
    const int nch = K >> 5;
    for (int ch = 0; ch < nch; ++ch) {
        int k0 = ch * BK;
        if (a_mn) load_mn(A, lda, Ar, k0, As_hi, As_lo, tid);
        else      load_kc(A, lda, Ar, k0, As_hi, As_lo, tid);
        if (b_mn) load_mn(B, ldb, Br, k0, Bs_hi, Bs_lo, tid);
        else      load_kc(B, ldb, Br, k0, Bs_hi, Bs_lo, tid);
        __syncthreads();

        #pragma unroll
        for (int s = 0; s < 2; ++s) {
            const int kb = s * 16 + (lane & 3) * 2;
            const int ar = lane >> 2;
            uint32_t ah[4][4], al[4][4];
            #pragma unroll
            for (int mi = 0; mi < 4; ++mi) {
                int r = m0 + mi * 16 + ar;
                ah[mi][0] = *(const uint32_t*)&As_hi[r * LROW + kb];
                ah[mi][1] = *(const uint32_t*)&As_hi[(r + 8) * LROW + kb];
                ah[mi][2] = *(const uint32_t*)&As_hi[r * LROW + kb + 8];
                ah[mi][3] = *(const uint32_t*)&As_hi[(r + 8) * LROW + kb + 8];
                al[mi][0] = *(const uint32_t*)&As_lo[r * LROW + kb];
                al[mi][1] = *(const uint32_t*)&As_lo[(r + 8) * LROW + kb];
                al[mi][2] = *(const uint32_t*)&As_lo[r * LROW + kb + 8];
                al[mi][3] = *(const uint32_t*)&As_lo[(r + 8) * LROW + kb + 8];
            }
            #pragma unroll
            for (int ni = 0; ni < 4; ++ni) {
                int n = n0 + ni * 8 + ar;
                uint32_t bh0 = *(const uint32_t*)&Bs_hi[n * LROW + kb];
                uint32_t bh1 = *(const uint32_t*)&Bs_hi[n * LROW + kb + 8];
                uint32_t bl0 = *(const uint32_t*)&Bs_lo[n * LROW + kb];
                uint32_t bl1 = *(const uint32_t*)&Bs_lo[n * LROW + kb + 8];
                #pragma unroll
                for (int mi = 0; mi < 4; ++mi) {
                    mma16816(acc[mi][ni], ah[mi][0], ah[mi][1], ah[mi][2], ah[mi][3], bh0, bh1);
                    mma16816(acc[mi][ni], ah[mi][0], ah[mi][1], ah[mi][2], ah[mi][3], bl0, bl1);
                    mma16816(acc[mi][ni], al[mi][0], al[mi][1], al[mi][2], al[mi][3], bh0, bh1);
                }
            }
        }
        __syncthreads();
    }

    // ---- epilogue ----
    const int gr = lane >> 2, gc = (lane & 3) * 2;
    #pragma unroll
    for (int mi = 0; mi < 4; ++mi) {
        #pragma unroll
        for (int ni = 0; ni < 4; ++ni) {
            int r = m0 + mi * 16 + gr;
            int c = n0 + ni * 8 + gc;
            if (r >= orows || c >= ocols) continue;
            float v0 = acc[mi][ni][0] * esc;
            float v1 = acc[mi][ni][1] * esc;
            float v2 = acc[mi][ni][2] * esc;
            float v3 = acc[mi][ni][3] * esc;
            if (bias) {
                float bl = bias[r], bh = bias[r + 8];
                v0 += bl; v1 += bl; v2 += bh; v3 += bh;
            }
            float2 p0 = {v0, v1}, p1 = {v2, v3};
            *(float2*)&eo[(size_t)r * ldo + c] = p0;
            *(float2*)&eo[(size_t)(r + 8) * ldo + c] = p1;
            if (em) {
                em[(size_t)c * ldo + r] = v0;
                em[(size_t)(c + 1) * ldo + r] = v1;
                em[(size_t)c * ldo + r + 8] = v2;
                em[(size_t)(c + 1) * ldo + r + 8] = v3;
            }
        }
    }
}

// ---------------- reduce split-K partials ----------------
__global__ void reduce_g() {
    int idx = blockIdx.x * 256 + threadIdx.x;            // 262144 float4s
    const size_t S = (size_t)BATCH * DIMC * DIMC / 4;
    const float4* p = (const float4*)g_Gp;
    float4 a = p[idx], b = p[idx + S], c = p[idx + 2 * S], d = p[idx + 3 * S];
    float4 r;
    r.x = a.x + b.x + c.x + d.x;
    r.y = a.y + b.y + c.y + d.y;
    r.z = a.z + b.z + c.z + d.z;
    r.w = a.w + b.w + c.w + d.w;
    ((float4*)g_G)[idx] = r;
}

// ---------------- launch ----------------
extern "C" void kernel_launch(void* const* d_in, const int* in_sizes, int n_in,
                              void* d_out, int out_size)
{
    const float* x     = (const float*)d_in[0];
    const float* w_qkv = (const float*)d_in[1];
    const float* w_out = (const float*)d_in[2];
    const float* b_out = (const float*)d_in[3];
    float* out = (float*)d_out;

    mma_kernel<<<192,  256>>>(MODE_SYRK,  x, w_qkv, w_out, b_out, out);
    reduce_g  <<<1024, 256>>>();
    mma_kernel<<<128,  256>>>(MODE_S1,    x, w_qkv, w_out, b_out, out);
    mma_kernel<<<128,  256>>>(MODE_S2,    x, w_qkv, w_out, b_out, out);
    mma_kernel<<<256,  256>>>(MODE_S3,    x, w_qkv, w_out, b_out, out);
    mma_kernel<<<64,   256>>>(MODE_S4,    x, w_qkv, w_out, b_out, out);
    mma_kernel<<<1024, 256>>>(MODE_FINAL, x, w_qkv, w_out, b_out, out);
}